// round 9
// baseline (speedup 1.0000x reference)
#include <cuda_runtime.h>
#include <math.h>

#define C_DIM 384
#define G_DIM 383
#define M_DIM 384
#define EPS_F 1e-5f
#define REP   64     // accumulator replicas (kills L2 atomic contention)
#define GPAD  512    // replica stride (2KB) -> distinct L2 line sets
#define XSPLIT 3     // k_reduce x-chunks per a
#define XCH   (M_DIM / XSPLIT)   // 128

// Scratch (no allocation allowed). Zero at module load; block (0,0) of
// k_reduce re-zeroes the replica arrays, the last-done block re-zeroes
// flag/partial/done -> every graph replay sees identical state.
__device__ float g_rsum[REP][GPAD];
__device__ float g_rssq[REP][GPAD];
__device__ int   g_rcnt[REP][GPAD];
__device__ float g_proto[M_DIM];
__device__ float g_std[M_DIM];
__device__ float g_partial;
__device__ int   g_done;
__device__ int   g_flag;

__device__ __forceinline__ float rcpa(float x) {
    float r;
    asm("rcp.approx.f32 %0, %1;" : "=f"(r) : "f"(x));
    return r;
}

// ---------------- Kernel 1: per-group count/sum/sumsq (2 rows per warp) -----
// Proven shape: ~80% DRAM (91% of LTS path ceiling). 3-level shuffle, lanes
// 0-3 REDG quarter-partials into this warp's replica. NO tail sync (R7 showed
// per-block fences at 80% DRAM cost ~20 us).
__global__ void __launch_bounds__(256) k_accum(const float4* __restrict__ pred,
                                               const int* __restrict__ tgt, int nrows) {
    int w    = (blockIdx.x * blockDim.x + threadIdx.x) >> 5;
    int lane = threadIdx.x & 31;
    int rep  = w & (REP - 1);
    int r0 = w * 2;
    if (r0 >= nrows) return;
    bool two = (r0 + 1) < nrows;

    const float4* rowA = pred + (size_t)r0 * (C_DIM / 4);
    const float4* rowB = rowA + (C_DIM / 4);

    float4 va[3], vb[3];
#pragma unroll
    for (int i = 0; i < 3; i++) va[i] = __ldcs(&rowA[lane + 32 * i]);
    if (two) {
#pragma unroll
        for (int i = 0; i < 3; i++) vb[i] = __ldcs(&rowB[lane + 32 * i]);
    } else {
#pragma unroll
        for (int i = 0; i < 3; i++) vb[i] = make_float4(0.f, 0.f, 0.f, 0.f);
    }

    float sA = 0.f, ssA = 0.f, sB = 0.f, ssB = 0.f;
#pragma unroll
    for (int i = 0; i < 3; i++) {
        sA += (va[i].x + va[i].y) + (va[i].z + va[i].w);
        ssA = fmaf(va[i].x, va[i].x, ssA);
        ssA = fmaf(va[i].y, va[i].y, ssA);
        ssA = fmaf(va[i].z, va[i].z, ssA);
        ssA = fmaf(va[i].w, va[i].w, ssA);
        sB += (vb[i].x + vb[i].y) + (vb[i].z + vb[i].w);
        ssB = fmaf(vb[i].x, vb[i].x, ssB);
        ssB = fmaf(vb[i].y, vb[i].y, ssB);
        ssB = fmaf(vb[i].z, vb[i].z, ssB);
        ssB = fmaf(vb[i].w, vb[i].w, ssB);
    }
#pragma unroll
    for (int o = 16; o >= 4; o >>= 1) {
        sA  += __shfl_down_sync(0xffffffffu, sA,  o);
        ssA += __shfl_down_sync(0xffffffffu, ssA, o);
        sB  += __shfl_down_sync(0xffffffffu, sB,  o);
        ssB += __shfl_down_sync(0xffffffffu, ssB, o);
    }

    int gA = tgt[r0];
    if (lane < 4) {
        atomicAdd(&g_rsum[rep][gA], sA);
        atomicAdd(&g_rssq[rep][gA], ssA);
    }
    if (lane == 0) atomicAdd(&g_rcnt[rep][gA], 1);
    if (two) {
        int gB = tgt[r0 + 1];
        if (lane < 4) {
            atomicAdd(&g_rsum[rep][gB], sB);
            atomicAdd(&g_rssq[rep][gB], ssB);
        }
        if (lane == 0) atomicAdd(&g_rcnt[rep][gB], 1);
    }
}

// ---------------- Kernel 2: fused stats + masked mean over M^3 -------------
// Block (0,0) folds the 64 replicas into proto/std (zeroing them), publishes
// via release-flag; all other blocks gate on an acquire-spin (block 0 is in
// wave 1 by placement, so no deadlock). Then block = (a, x-chunk), thread = b:
// w/(nrm+w) = 1 - nrm/(nrm+w) with FOUR reciprocals fused per MUFU.RCP.
__global__ void __launch_bounds__(M_DIM) k_reduce(float* __restrict__ out) {
    __shared__ float  sp[M_DIM];
    __shared__ float4 su4[XCH / 4];
    __shared__ float  red[M_DIM / 32];
    __shared__ int    isLast;

    const float SQC = 19.595917942265423f;  // sqrt(384)
    int a   = blockIdx.x;
    int xc  = blockIdx.y;
    int tid = threadIdx.x;

    if (a == 0 && xc == 0) {
        // ---- stats fold: replicas -> proto/std, re-zero replicas ----
        int g = tid;
        float mean = 0.f, sd = 0.f;
        if (g < G_DIM) {
            float sum = 0.f, ssq = 0.f;
            int   cnt = 0;
#pragma unroll 8
            for (int r = 0; r < REP; r++) {
                sum += g_rsum[r][g];
                ssq += g_rssq[r][g];
                cnt += g_rcnt[r][g];
            }
#pragma unroll 8
            for (int r = 0; r < REP; r++) {
                g_rsum[r][g] = 0.f;
                g_rssq[r][g] = 0.f;
                g_rcnt[r][g] = 0;
            }
            float n = (float)cnt;
            if (n > 0.f) {
                float tot = n * (float)C_DIM;
                mean = sum / tot;
                float s2 = ssq - sum * mean;     // sumsq - sum^2/tot
                if (s2 < 0.f) s2 = 0.f;
                sd = (n > 1.f) ? sqrtf(s2 / fmaxf(tot - 1.f, 1.f)) : 0.f;
            }
        }
        g_proto[g] = mean;   // slot 383 stays 0 (padded object slot)
        g_std[g]   = sd;
        __threadfence();
        __syncthreads();
        if (tid == 0)
            asm volatile("st.release.gpu.global.b32 [%0], %1;"
                         :: "l"(&g_flag), "r"(1) : "memory");
    } else {
        if (tid == 0) {
            int f;
            do {
                asm volatile("ld.acquire.gpu.global.b32 %0, [%1];"
                             : "=r"(f) : "l"(&g_flag) : "memory");
                if (!f) __nanosleep(128);
            } while (!f);
        }
        __syncthreads();
    }

    sp[tid] = g_proto[tid];
    __syncthreads();

    float pa = sp[a];
    if (tid < XCH) {
        float d = fabsf(sp[xc * XCH + tid] - pa);
        ((float*)su4)[tid] = d * rcpa(fmaf(SQC, d, EPS_F));  // 0 when x==a
    }
    __syncthreads();

    float part = 0.f;
    int b = tid;
    if (b > a) {
        float sab = g_std[a] + g_std[b];
        float nrm = fmaf(SQC, fabsf(sp[b] - pa), EPS_F);
#pragma unroll 8
        for (int i = 0; i < XCH / 4; i++) {
            float4 u = su4[i];                 // warp-broadcast LDS
            float d0 = fmaf(sab, u.x, nrm);
            float d1 = fmaf(sab, u.y, nrm);
            float d2 = fmaf(sab, u.z, nrm);
            float d3 = fmaf(sab, u.w, nrm);
            float p01 = d0 * d1;
            float p23 = d2 * d3;
            float num = fmaf(d2 + d3, p01, (d0 + d1) * p23);
            part = fmaf(num, rcpa(p01 * p23), part);   // += 1/d0+1/d1+1/d2+1/d3
        }
        part = (float)XCH - nrm * part;        // Sum_x w/(nrm+w) over chunk
    }

    // block reduction (12 warps)
#pragma unroll
    for (int o = 16; o; o >>= 1) part += __shfl_down_sync(0xffffffffu, part, o);
    if ((tid & 31) == 0) red[tid >> 5] = part;
    __syncthreads();
    if (tid == 0) {
        float v = 0.f;
#pragma unroll
        for (int i = 0; i < M_DIM / 32; i++) v += red[i];
        atomicAdd(&g_partial, v);
        __threadfence();
        int t = atomicAdd(&g_done, 1);
        isLast = (t == (int)(gridDim.x * gridDim.y) - 1);
    }
    __syncthreads();

    if (isLast && tid == 0) {
        // All blocks passed the gate (their done-increment follows it), so
        // resetting the flag here is safe for the next replay.
        const float inv_m3 = 1.0f / ((float)M_DIM * (float)M_DIM * (float)M_DIM);
        out[0] = g_partial * inv_m3;
        g_partial = 0.f;
        g_done = 0;
        g_flag = 0;
    }
}

extern "C" void kernel_launch(void* const* d_in, const int* in_sizes, int n_in,
                              void* d_out, int out_size) {
    const float* pred = (const float*)d_in[0];
    const int*   tgt  = (const int*)d_in[1];
    float*       out  = (float*)d_out;
    int nrows = in_sizes[1];                // 200000

    int warps  = (nrows + 1) / 2;           // 2 rows per warp, one-shot blocks
    int blocks = (warps * 32 + 255) / 256;
    k_accum<<<blocks, 256>>>((const float4*)pred, tgt, nrows);
    k_reduce<<<dim3(G_DIM, XSPLIT), M_DIM>>>(out);
    // 2 launches/call -> ncu (index 3) captures the fused k_reduce next.
}

// round 10
// speedup vs baseline: 1.0803x; 1.0803x over previous
#include <cuda_runtime.h>
#include <math.h>

#define C_DIM 384
#define G_DIM 383
#define M_DIM 384
#define EPS_F 1e-5f
#define REP   64     // accumulator replicas (kills L2 atomic contention)
#define GPAD  512    // replica stride (2KB) -> distinct L2 line sets
#define XSPLIT 3     // k_reduce x-chunks per a-pair
#define XCH   (M_DIM / XSPLIT)   // 128
#define PAIRS 192    // a-pair blocks: (a, 382-a) for a=0..190, plus a=191 solo

// Scratch (no allocation allowed). Zero at module load; k_stats re-zeroes the
// replica arrays, k_reduce re-zeroes g_partial/g_done every call, so each
// graph replay sees identical state.
__device__ float g_rsum[REP][GPAD];
__device__ float g_rssq[REP][GPAD];
__device__ int   g_rcnt[REP][GPAD];
__device__ float g_proto[M_DIM];
__device__ float g_std[M_DIM];
__device__ float g_partial;
__device__ int   g_done;

__device__ __forceinline__ float rcpa(float x) {
    float r;
    asm("rcp.approx.f32 %0, %1;" : "=f"(r) : "f"(x));
    return r;
}

// ---------------- Kernel 1: per-group count/sum/sumsq (2 rows per warp) -----
// Frozen shape: ~80% DRAM (86% of practical stream ceiling). 3-level shuffle,
// lanes 0-3 REDG quarter-partials into this warp's replica.
__global__ void __launch_bounds__(256) k_accum(const float4* __restrict__ pred,
                                               const int* __restrict__ tgt, int nrows) {
    int w    = (blockIdx.x * blockDim.x + threadIdx.x) >> 5;
    int lane = threadIdx.x & 31;
    int rep  = w & (REP - 1);
    int r0 = w * 2;
    if (r0 >= nrows) return;
    bool two = (r0 + 1) < nrows;

    const float4* rowA = pred + (size_t)r0 * (C_DIM / 4);
    const float4* rowB = rowA + (C_DIM / 4);

    float4 va[3], vb[3];
#pragma unroll
    for (int i = 0; i < 3; i++) va[i] = __ldcs(&rowA[lane + 32 * i]);
    if (two) {
#pragma unroll
        for (int i = 0; i < 3; i++) vb[i] = __ldcs(&rowB[lane + 32 * i]);
    } else {
#pragma unroll
        for (int i = 0; i < 3; i++) vb[i] = make_float4(0.f, 0.f, 0.f, 0.f);
    }

    float sA = 0.f, ssA = 0.f, sB = 0.f, ssB = 0.f;
#pragma unroll
    for (int i = 0; i < 3; i++) {
        sA += (va[i].x + va[i].y) + (va[i].z + va[i].w);
        ssA = fmaf(va[i].x, va[i].x, ssA);
        ssA = fmaf(va[i].y, va[i].y, ssA);
        ssA = fmaf(va[i].z, va[i].z, ssA);
        ssA = fmaf(va[i].w, va[i].w, ssA);
        sB += (vb[i].x + vb[i].y) + (vb[i].z + vb[i].w);
        ssB = fmaf(vb[i].x, vb[i].x, ssB);
        ssB = fmaf(vb[i].y, vb[i].y, ssB);
        ssB = fmaf(vb[i].z, vb[i].z, ssB);
        ssB = fmaf(vb[i].w, vb[i].w, ssB);
    }
#pragma unroll
    for (int o = 16; o >= 4; o >>= 1) {
        sA  += __shfl_down_sync(0xffffffffu, sA,  o);
        ssA += __shfl_down_sync(0xffffffffu, ssA, o);
        sB  += __shfl_down_sync(0xffffffffu, sB,  o);
        ssB += __shfl_down_sync(0xffffffffu, ssB, o);
    }

    int gA = tgt[r0];
    if (lane < 4) {
        atomicAdd(&g_rsum[rep][gA], sA);
        atomicAdd(&g_rssq[rep][gA], ssA);
    }
    if (lane == 0) atomicAdd(&g_rcnt[rep][gA], 1);
    if (two) {
        int gB = tgt[r0 + 1];
        if (lane < 4) {
            atomicAdd(&g_rsum[rep][gB], sB);
            atomicAdd(&g_rssq[rep][gB], ssB);
        }
        if (lane == 0) atomicAdd(&g_rcnt[rep][gB], 1);
    }
}

// ---------------- Kernel 2: fold replicas -> proto/std, re-zero replicas ----
__global__ void __launch_bounds__(M_DIM) k_stats() {
    int g = threadIdx.x;
    float mean = 0.f, sd = 0.f;
    if (g < G_DIM) {
        float sum = 0.f, ssq = 0.f;
        int   cnt = 0;
#pragma unroll 8
        for (int r = 0; r < REP; r++) {
            sum += g_rsum[r][g];
            ssq += g_rssq[r][g];
            cnt += g_rcnt[r][g];
        }
#pragma unroll 8
        for (int r = 0; r < REP; r++) {
            g_rsum[r][g] = 0.f;
            g_rssq[r][g] = 0.f;
            g_rcnt[r][g] = 0;
        }
        float n = (float)cnt;
        if (n > 0.f) {
            float tot = n * (float)C_DIM;
            mean = sum / tot;
            float s2 = ssq - sum * mean;      // sumsq - sum^2/tot
            if (s2 < 0.f) s2 = 0.f;
            sd = (n > 1.f) ? sqrtf(s2 / fmaxf(tot - 1.f, 1.f)) : 0.f;
        }
    }
    g_proto[g] = mean;   // slot 383 stays 0 (padded object slot)
    g_std[g]   = sd;
}

// ---------------- Kernel 3: masked mean over M^3, paired a-blocks ----------
// Block (pb, xc) handles a1 = pb and a2 = 382-pb over x-chunk xc. Since
// (383-a1)+(383-a2) = 384 = blockDim, EVERY thread owns exactly one (a,b)
// assignment -> zero idle lanes (vs 50% idle with the plain b>a mask).
// Inner loop over x uses w/(nrm+w) = 1 - nrm/(nrm+w) with FOUR reciprocals
// fused per MUFU.RCP. pb=191 (a1==a2) deactivates its duplicate half.
__global__ void __launch_bounds__(M_DIM) k_reduce(float* __restrict__ out) {
    __shared__ float  sp[M_DIM];
    __shared__ float  ssd[M_DIM];
    __shared__ float4 su1[XCH / 4];
    __shared__ float4 su2[XCH / 4];
    __shared__ float  red[M_DIM / 32];
    __shared__ int    isLast;

    const float SQC = 19.595917942265423f;  // sqrt(384)
    int pb  = blockIdx.x;       // 0..191
    int xc  = blockIdx.y;
    int tid = threadIdx.x;
    int a1  = pb;
    int a2  = 382 - pb;         // == a1 when pb == 191

    sp[tid]  = g_proto[tid];
    ssd[tid] = g_std[tid];
    __syncthreads();

    float p1 = sp[a1];
    float p2 = sp[a2];
    if (tid < XCH) {
        float d = fabsf(sp[xc * XCH + tid] - p1);
        ((float*)su1)[tid] = d * rcpa(fmaf(SQC, d, EPS_F));   // 0 when x==a1
    } else if (tid < 2 * XCH) {
        int t = tid - XCH;
        float d = fabsf(sp[xc * XCH + t] - p2);
        ((float*)su2)[t] = d * rcpa(fmaf(SQC, d, EPS_F));     // 0 when x==a2
    }
    __syncthreads();

    // thread -> (a_sel, b) assignment: first L1 threads serve a1, rest a2
    int  L1     = 383 - a1;
    bool first  = tid < L1;
    bool active = first | (a1 != a2);       // pb=191: drop duplicate half
    int  b      = first ? (a1 + 1 + tid) : (a2 + 1 + (tid - L1));

    float part = 0.f;
    if (active) {
        float pa  = first ? p1 : p2;
        float sab = (first ? ssd[a1] : ssd[a2]) + ssd[b];
        float nrm = fmaf(SQC, fabsf(sp[b] - pa), EPS_F);
        const float4* su = first ? su1 : su2;
#pragma unroll 8
        for (int i = 0; i < XCH / 4; i++) {
            float4 u = su[i];                  // warp-broadcast (2-way worst)
            float d0 = fmaf(sab, u.x, nrm);
            float d1 = fmaf(sab, u.y, nrm);
            float d2 = fmaf(sab, u.z, nrm);
            float d3 = fmaf(sab, u.w, nrm);
            float p01 = d0 * d1;
            float p23 = d2 * d3;
            float num = fmaf(d2 + d3, p01, (d0 + d1) * p23);
            part = fmaf(num, rcpa(p01 * p23), part);  // += Σ 1/d_i
        }
        part = (float)XCH - nrm * part;        // Σ_x w/(nrm+w) over chunk
    }

    // block reduction (12 warps)
#pragma unroll
    for (int o = 16; o; o >>= 1) part += __shfl_down_sync(0xffffffffu, part, o);
    if ((tid & 31) == 0) red[tid >> 5] = part;
    __syncthreads();
    if (tid == 0) {
        float v = 0.f;
#pragma unroll
        for (int i = 0; i < M_DIM / 32; i++) v += red[i];
        atomicAdd(&g_partial, v);
        __threadfence();
        int t = atomicAdd(&g_done, 1);
        isLast = (t == (int)(gridDim.x * gridDim.y) - 1);
    }
    __syncthreads();

    if (isLast && tid == 0) {
        const float inv_m3 = 1.0f / ((float)M_DIM * (float)M_DIM * (float)M_DIM);
        out[0] = g_partial * inv_m3;
        g_partial = 0.f;
        g_done = 0;
    }
}

extern "C" void kernel_launch(void* const* d_in, const int* in_sizes, int n_in,
                              void* d_out, int out_size) {
    const float* pred = (const float*)d_in[0];
    const int*   tgt  = (const int*)d_in[1];
    float*       out  = (float*)d_out;
    int nrows = in_sizes[1];                // 200000

    int warps  = (nrows + 1) / 2;           // 2 rows per warp, one-shot blocks
    int blocks = (warps * 32 + 255) / 256;
    k_accum<<<blocks, 256>>>((const float4*)pred, tgt, nrows);
    k_stats<<<1, M_DIM>>>();
    k_reduce<<<dim3(PAIRS, XSPLIT), M_DIM>>>(out);
}